// round 16
// baseline (speedup 1.0000x reference)
#include <cuda_runtime.h>
#include <cuda_fp16.h>
#include <cstdint>

#define T_DIM   8192
#define IN_DIM  4096
#define OUT_DIM 4096
#define R_DIM   256
#define SCALE_F 4.0f
#define NSM     148
#define NTILES  1024   /* main: 16 (o/256) x 64 (t/128) */
#define WGROUP  80     /* phase-B CTAs doing weff; rest do xprep */
#define BLK     512

// Tiled + SW128-pre-swizzled fp16 operand buffers (16KB tiles: 128 rows x 64 cols)
__device__ __align__(128) __half g_xhi[(size_t)T_DIM  * IN_DIM];
__device__ __align__(128) __half g_whi[(size_t)OUT_DIM * IN_DIM];
__device__ __align__(128) __half g_bh [(size_t)OUT_DIM * R_DIM];
__device__ __align__(128) __half g_ahT[(size_t)IN_DIM  * R_DIM];

// monotonic grid-barrier counter (replay-safe: target = ceil(ticket/NSM)*NSM)
__device__ int g_ctr;

// ---------------------------------------------------------------------------
// helpers
// ---------------------------------------------------------------------------
static __device__ __forceinline__ uint32_t sw128(uint32_t b) {
    return b ^ ((b >> 3) & 0x70);
}
static __device__ __forceinline__ uint32_t smem_u32(const void* p) {
    uint32_t a;
    asm("{ .reg .u64 t; cvta.to.shared.u64 t, %1; cvt.u32.u64 %0, t; }"
        : "=r"(a) : "l"(p));
    return a;
}
static __device__ __forceinline__ uint32_t h2u(__half a, __half b) {
    __half2 h = __halves2half2(a, b);
    return *(uint32_t*)&h;
}

#define MBARRIER_INIT(m, c) \
    asm volatile("mbarrier.init.shared.b64 [%0], %1;" :: "r"(m), "r"((uint32_t)(c)) : "memory")
#define MBARRIER_EXPECT_TX(m, b) \
    asm volatile("mbarrier.arrive.expect_tx.shared.b64 _, [%0], %1;" :: "r"(m), "r"((uint32_t)(b)) : "memory")
#define MBARRIER_ARRIVE(m) \
    asm volatile("mbarrier.arrive.shared.b64 _, [%0];" :: "r"(m) : "memory")

#define WAIT_PARITY(m, p) do {                                                    \
    uint32_t _m = (m), _p = (uint32_t)(p), _d;                                    \
    asm volatile("{\n\t.reg .pred P;\n\t"                                         \
        "mbarrier.try_wait.parity.acquire.cta.shared::cta.b64 P, [%1], %2;\n\t"   \
        "selp.b32 %0, 1, 0, P;\n\t}" : "=r"(_d) : "r"(_m), "r"(_p) : "memory");   \
    while (!_d) {                                                                 \
        asm volatile("{\n\t.reg .pred P;\n\t"                                     \
            "mbarrier.try_wait.parity.acquire.cta.shared::cta.b64 P, [%1], %2, 0x989680;\n\t" \
            "selp.b32 %0, 1, 0, P;\n\t}" : "=r"(_d) : "r"(_m), "r"(_p) : "memory"); \
    } } while (0)

static __device__ __forceinline__ void bulk_g2s(uint32_t dst, const void* src,
                                                uint32_t bytes, uint32_t mbar) {
    unsigned long long g = (unsigned long long)__cvta_generic_to_global(src);
    asm volatile("cp.async.bulk.shared::cta.global.mbarrier::complete_tx::bytes [%0], [%1], %2, [%3];"
                 :: "r"(dst), "l"(g), "r"(bytes), "r"(mbar) : "memory");
}

#define LDSM_X4(r, addr) \
    asm volatile("ldmatrix.sync.aligned.m8n8.x4.shared.b16 {%0,%1,%2,%3}, [%4];" \
                 : "=r"((r)[0]), "=r"((r)[1]), "=r"((r)[2]), "=r"((r)[3]) : "r"(addr))

#define MMA16816(c, a, b0, b1) \
    asm volatile("mma.sync.aligned.m16n8k16.row.col.f32.f16.f16.f32 " \
                 "{%0,%1,%2,%3}, {%4,%5,%6,%7}, {%8,%9}, {%0,%1,%2,%3};" \
                 : "+f"((c)[0]), "+f"((c)[1]), "+f"((c)[2]), "+f"((c)[3]) \
                 : "r"((a)[0]), "r"((a)[1]), "r"((a)[2]), "r"((a)[3]), \
                   "r"(b0), "r"(b1))

// device-wide barrier (all NSM CTAs resident at 1/SM)
static __device__ __forceinline__ void grid_bar() {
    __threadfence();
    __syncthreads();
    __shared__ int s_tgt;
    if (threadIdx.x == 0) {
        int t = atomicAdd(&g_ctr, 1) + 1;
        s_tgt = ((t + NSM - 1) / NSM) * NSM;
    }
    __syncthreads();
    if (threadIdx.x == 0) {
        const int tgt = s_tgt;
        int v;
        do {
            asm volatile("ld.global.acquire.gpu.b32 %0, [%1];" : "=r"(v) : "l"(&g_ctr));
        } while (v < tgt);
    }
    __syncthreads();
}

#define STAGES    4
#define STAGE_B   49152
#define WSTG_B    32768
#define SMEM_MAIN (1024 + STAGES * STAGE_B)

__global__ __launch_bounds__(BLK, 1) void vera_all(
    const float* __restrict__ x,  const float* __restrict__ W,
    const float* __restrict__ vA, const float* __restrict__ vB,
    const float* __restrict__ vd, const float* __restrict__ vb,
    const float* __restrict__ bias, float* __restrict__ y)
{
    extern __shared__ char smem[];
    const uint32_t sb = smem_u32(smem);
    const int tid  = threadIdx.x;
    const int lane = tid & 31;
    const int wid  = tid >> 5;            // 0..15
    const int bid  = blockIdx.x;

    const uint32_t FULL   = sb;
    const uint32_t EMPTY  = sb + 32;
    const uint32_t FULLB  = sb + 64;
    const uint32_t EMPTYB = sb + 112;
    const uint32_t STG0   = sb + 1024;

    if (tid == 0) {
        for (int s = 0; s < STAGES; s++) {
            MBARRIER_INIT(FULL  + 8 * s, 1);
            MBARRIER_INIT(EMPTY + 8 * s, 16);   // 16 consumer warps
        }
        for (int s = 0; s < 6; s++) {
            MBARRIER_INIT(FULLB  + 8 * s, 1);
            MBARRIER_INIT(EMPTYB + 8 * s, 8);   // weff uses warps 0-7
        }
    }
    __syncthreads();

    // ======================= PHASE A: Bh + AhT conversion ===================
    for (uint32_t c = bid * BLK + tid; c < 131072; c += NSM * BLK) {
        const uint32_t o    = c >> 5;
        const uint32_t r8   = c & 31;
        const uint32_t rblk = r8 >> 3;
        const uint32_t cu   = (r8 & 7) * 8;
        const float s = __ldg(&vb[o]) * (SCALE_F / 64.0f);
        const float* src = vB + (size_t)o * R_DIM + rblk * 64 + cu;
        float4 a = *(const float4*)src;
        float4 b = *(const float4*)(src + 4);
        __half h[8] = {__float2half_rn(a.x * s), __float2half_rn(a.y * s),
                       __float2half_rn(a.z * s), __float2half_rn(a.w * s),
                       __float2half_rn(b.x * s), __float2half_rn(b.y * s),
                       __float2half_rn(b.z * s), __float2half_rn(b.w * s)};
        uint4 v = make_uint4(h2u(h[0], h[1]), h2u(h[2], h[3]),
                             h2u(h[4], h[5]), h2u(h[6], h[7]));
        const size_t tile = ((size_t)(o >> 7) * 4 + rblk) * 16384;
        *(uint4*)((char*)g_bh + tile + sw128((o & 127) * 128 + cu * 2)) = v;
    }
    for (uint32_t c = bid * BLK + tid; c < 131072; c += NSM * BLK) {
        const uint32_t r8 = c >> 12;
        const uint32_t i  = c & 4095;
        uint32_t pk[4];
#pragma unroll
        for (int j = 0; j < 4; j++) {
            const uint32_t r0 = r8 * 8 + 2 * j;
            const float s0 = __ldg(&vd[r0])     * 64.0f;
            const float s1 = __ldg(&vd[r0 + 1]) * 64.0f;
            const float v0 = __ldg(&vA[(size_t)r0 * IN_DIM + i])       * s0;
            const float v1 = __ldg(&vA[(size_t)(r0 + 1) * IN_DIM + i]) * s1;
            pk[j] = h2u(__float2half_rn(v0), __float2half_rn(v1));
        }
        const size_t tile = ((size_t)(i >> 7) * 4 + (r8 >> 3)) * 16384;
        const uint32_t off = sw128((i & 127) * 128 + (r8 & 7) * 16);
        *(uint4*)((char*)g_ahT + tile + off) = make_uint4(pk[0], pk[1], pk[2], pk[3]);
    }

    grid_bar();

    // ============ PHASE B: weff HMMA (bid<WGROUP, warps 0-7) || xprep =======
    if (bid < WGROUP) {
        if (wid < 8) {
            const int ntB   = (1023 - bid) / WGROUP + 1;  // 12 or 13
            const int NITB  = ntB * 4;

            if (lane == 0 && wid < 6) {
                const int q = wid;
                const int tile = bid + (q >> 2) * WGROUP;
                const int k    = q & 3;
                const uint32_t base = STG0 + wid * WSTG_B;
                MBARRIER_EXPECT_TX(FULLB + 8 * wid, WSTG_B);
                bulk_g2s(base,         (char*)g_bh  + (size_t)((tile >> 5) * 4 + k) * 16384, 16384, FULLB + 8 * wid);
                bulk_g2s(base + 16384, (char*)g_ahT + (size_t)((tile & 31) * 4 + k) * 16384, 16384, FULLB + 8 * wid);
            }

            const int warp_m = wid >> 2;   // 0..1
            const int warp_n = wid & 3;    // 0..3
            const int a_row      = warp_m * 64 + (lane & 15);
            const uint32_t a_rb  = (uint32_t)a_row * 128;
            const uint32_t amsk  = (uint32_t)(lane & 7) << 4;
            const uint32_t acol0 = (uint32_t)(lane >> 4) * 16;
            const int b_rowl     = warp_n * 32 + (lane & 7) + ((lane >> 4) & 1) * 8;
            const uint32_t b_rb  = (uint32_t)b_rowl * 128;
            const uint32_t bmsk  = (uint32_t)(lane & 7) << 4;
            const uint32_t bcol0 = (uint32_t)((lane >> 3) & 1) * 16;

            float acc[4][4][4];
#pragma unroll
            for (int i = 0; i < 4; i++)
#pragma unroll
                for (int t = 0; t < 4; t++)
#pragma unroll
                    for (int q = 0; q < 4; q++) acc[i][t][q] = 0.0f;

#pragma unroll 1
            for (int p = 0; p < NITB; ++p) {
                const int s  = p % 6;
                const int ph = (p / 6) & 1;
                WAIT_PARITY(FULLB + 8 * s, ph);
                const uint32_t XA = STG0 + s * WSTG_B;
                const uint32_t WB = XA + 16384;
#pragma unroll
                for (int ks = 0; ks < 4; ks++) {
                    const uint32_t acsw = (acol0 + ks * 32) ^ amsk;
                    const uint32_t bcsw = (bcol0 + ks * 32) ^ bmsk;
                    uint32_t A[4][4], B[2][4];
#pragma unroll
                    for (int i = 0; i < 4; i++)
                        LDSM_X4(A[i], XA + a_rb + i * 2048 + acsw);
#pragma unroll
                    for (int j = 0; j < 2; j++)
                        LDSM_X4(B[j], WB + b_rb + j * 2048 + bcsw);
#pragma unroll
                    for (int i = 0; i < 4; i++)
#pragma unroll
                        for (int j = 0; j < 2; j++) {
                            MMA16816(acc[i][2 * j],     A[i], B[j][0], B[j][1]);
                            MMA16816(acc[i][2 * j + 1], A[i], B[j][2], B[j][3]);
                        }
                }
                __syncwarp();
                if (lane == 0) MBARRIER_ARRIVE(EMPTYB + 8 * s);

                if (wid == s && lane == 0 && p + 6 < NITB) {
                    WAIT_PARITY(EMPTYB + 8 * s, ph);
                    const int q    = p + 6;
                    const int tile = bid + (q >> 2) * WGROUP;
                    const int k    = q & 3;
                    const uint32_t base = STG0 + s * WSTG_B;
                    MBARRIER_EXPECT_TX(FULLB + 8 * s, WSTG_B);
                    bulk_g2s(base,         (char*)g_bh  + (size_t)((tile >> 5) * 4 + k) * 16384, 16384, FULLB + 8 * s);
                    bulk_g2s(base + 16384, (char*)g_ahT + (size_t)((tile & 31) * 4 + k) * 16384, 16384, FULLB + 8 * s);
                }

                if ((p & 3) == 3) {   // tile epilogue: Weff = W + delta -> g_whi
                    const int tile = bid + (p >> 2) * WGROUP;
                    const int bO = tile >> 5;
                    const int bI = tile & 31;
                    const int trow0 = warp_m * 64 + (lane >> 2);
                    const int col0  = warp_n * 32 + (lane & 3) * 2;
#pragma unroll
                    for (int t = 0; t < 4; t++) {
                        const int col = col0 + t * 8;
                        const int ig  = bI * 128 + col;
                        const size_t gtile = ((size_t)bO * 64 + (ig >> 6)) * 16384;
                        const uint32_t cu2 = (uint32_t)(ig & 63) * 2;
#pragma unroll
                        for (int i = 0; i < 4; i++) {
                            const int r0 = trow0 + i * 16;
                            const float2 w0 = *(const float2*)&W[(size_t)(bO * 128 + r0) * IN_DIM + ig];
                            const float2 w1 = *(const float2*)&W[(size_t)(bO * 128 + r0 + 8) * IN_DIM + ig];
                            const uint32_t v0 = h2u(__float2half_rn(w0.x + acc[i][t][0]),
                                                    __float2half_rn(w0.y + acc[i][t][1]));
                            const uint32_t v1 = h2u(__float2half_rn(w1.x + acc[i][t][2]),
                                                    __float2half_rn(w1.y + acc[i][t][3]));
                            *(uint32_t*)((char*)g_whi + gtile + sw128((uint32_t)r0 * 128 + cu2))       = v0;
                            *(uint32_t*)((char*)g_whi + gtile + sw128((uint32_t)(r0 + 8) * 128 + cu2)) = v1;
                        }
                    }
#pragma unroll
                    for (int i = 0; i < 4; i++)
#pragma unroll
                        for (int t = 0; t < 4; t++)
#pragma unroll
                            for (int q = 0; q < 4; q++) acc[i][t][q] = 0.0f;
                }
            }
        }
        // warps 8-15 of weff CTAs fall through (idle during weff)
    } else {
        // xprep on 68 CTAs, all 512 threads
        for (uint32_t c = (uint32_t)(bid - WGROUP) * BLK + tid; c < 4194304u;
             c += (uint32_t)(NSM - WGROUP) * BLK) {
            const uint32_t k8   = c & 511;
            const uint32_t t    = c >> 9;
            const uint32_t kblk = k8 >> 3;
            const uint32_t cu   = (k8 & 7) * 8;
            const float* src = x + (size_t)t * IN_DIM + kblk * 64 + cu;
            float4 a = *(const float4*)src;
            float4 b = *(const float4*)(src + 4);
            __half2 p0 = __floats2half2_rn(a.x, a.y);
            __half2 p1 = __floats2half2_rn(a.z, a.w);
            __half2 p2 = __floats2half2_rn(b.x, b.y);
            __half2 p3 = __floats2half2_rn(b.z, b.w);
            uint4 v = make_uint4(*(uint32_t*)&p0, *(uint32_t*)&p1,
                                 *(uint32_t*)&p2, *(uint32_t*)&p3);
            const uint32_t off = sw128((t & 127) * 128 + cu * 2);
            *(uint4*)((char*)g_xhi + ((size_t)(t >> 7) * 64 + kblk) * 16384 + off) = v;
        }
    }

    grid_bar();

    // ============ PHASE C: main GEMM, 16 warps (4M x 4N, warp tile 32x64) ===
    const int ntile = (NTILES - 1 - bid) / NSM + 1;   // 6 or 7
    const int NITER = ntile * 64;

    if (lane == 0 && wid < STAGES) {
        const int s = wid;
        const char* xs = (const char*)g_xhi + (size_t)((bid >> 4) * 64 + s) * 16384;
        const char* ws = (const char*)g_whi + (size_t)((bid & 15) * 2 * 64 + s) * 16384;
        const uint32_t base = STG0 + s * STAGE_B;
        MBARRIER_EXPECT_TX(FULL + 8 * s, STAGE_B);
        bulk_g2s(base,         xs, 16384, FULL + 8 * s);
        bulk_g2s(base + 16384, ws, 16384, FULL + 8 * s);
        bulk_g2s(base + 32768, ws + (size_t)64 * 16384, 16384, FULL + 8 * s);
    }

    const int warp_m = wid >> 2;   // 0..3 (32 t-rows each)
    const int warp_n = wid & 3;    // 0..3 (64 o-cols each)

    const int a_row      = warp_m * 32 + (lane & 15);
    const uint32_t a_rb  = (uint32_t)a_row * 128;
    const uint32_t amsk  = (uint32_t)(lane & 7) << 4;
    const uint32_t acol0 = (uint32_t)(lane >> 4) * 16;

    const int b_rowl     = (warp_n & 1) * 64 + (lane & 7) + ((lane >> 4) & 1) * 8;
    const uint32_t b_rb  = (uint32_t)((warp_n >> 1) * 16384 + b_rowl * 128);
    const uint32_t bmsk  = (uint32_t)(lane & 7) << 4;
    const uint32_t bcol0 = (uint32_t)((lane >> 3) & 1) * 16;

    float acc[2][8][4];
#pragma unroll
    for (int i = 0; i < 2; i++)
#pragma unroll
        for (int t = 0; t < 8; t++)
#pragma unroll
            for (int q = 0; q < 4; q++) acc[i][t][q] = 0.0f;

#pragma unroll 1
    for (int p = 0; p < NITER; ++p) {
        const int s  = p & 3;
        const int ph = (p >> 2) & 1;
        WAIT_PARITY(FULL + 8 * s, ph);
        const uint32_t XA = STG0 + s * STAGE_B;
        const uint32_t WB = XA + 16384;

#pragma unroll
        for (int ks = 0; ks < 4; ks++) {
            const uint32_t acsw = (acol0 + ks * 32) ^ amsk;
            const uint32_t bcsw = (bcol0 + ks * 32) ^ bmsk;
            uint32_t A[2][4], B[4][4];
#pragma unroll
            for (int i = 0; i < 2; i++)
                LDSM_X4(A[i], XA + a_rb + i * 2048 + acsw);
#pragma unroll
            for (int j = 0; j < 4; j++)
                LDSM_X4(B[j], WB + b_rb + j * 2048 + bcsw);
#pragma unroll
            for (int i = 0; i < 2; i++)
#pragma unroll
                for (int j = 0; j < 4; j++) {
                    MMA16816(acc[i][2 * j],     A[i], B[j][0], B[j][1]);
                    MMA16816(acc[i][2 * j + 1], A[i], B[j][2], B[j][3]);
                }
        }

        __syncwarp();
        if (lane == 0) MBARRIER_ARRIVE(EMPTY + 8 * s);

        // stage-distributed refill: warp s owns stage s (s in 0..3)
        if (wid == s && lane == 0 && p + STAGES < NITER) {
            WAIT_PARITY(EMPTY + 8 * s, ph);
            const int q    = p + STAGES;
            const int tile = bid + (q >> 6) * NSM;
            const int k    = q & 63;
            const char* xs = (const char*)g_xhi + (size_t)((tile >> 4) * 64 + k) * 16384;
            const char* ws = (const char*)g_whi + (size_t)((tile & 15) * 2 * 64 + k) * 16384;
            const uint32_t base = STG0 + s * STAGE_B;
            MBARRIER_EXPECT_TX(FULL + 8 * s, STAGE_B);
            bulk_g2s(base,         xs, 16384, FULL + 8 * s);
            bulk_g2s(base + 16384, ws, 16384, FULL + 8 * s);
            bulk_g2s(base + 32768, ws + (size_t)64 * 16384, 16384, FULL + 8 * s);
        }

        // tile epilogue
        if ((p & 63) == 63) {
            const int tile = bid + (p >> 6) * NSM;
            const int bM = tile >> 4;
            const int bN = tile & 15;
            const int trow0 = bM * 128 + warp_m * 32 + (lane >> 2);
            const int col0g = bN * 256 + warp_n * 64 + (lane & 3) * 2;
#pragma unroll
            for (int t = 0; t < 8; t++) {
                const int col = col0g + t * 8;
                const float2 bv = *(const float2*)&bias[col];
#pragma unroll
                for (int i = 0; i < 2; i++) {
                    const int r0 = trow0 + i * 16;
                    float2 o0 = make_float2(acc[i][t][0] + bv.x, acc[i][t][1] + bv.y);
                    float2 o1 = make_float2(acc[i][t][2] + bv.x, acc[i][t][3] + bv.y);
                    *(float2*)&y[(size_t)r0 * OUT_DIM + col]       = o0;
                    *(float2*)&y[(size_t)(r0 + 8) * OUT_DIM + col] = o1;
                }
            }
#pragma unroll
            for (int i = 0; i < 2; i++)
#pragma unroll
                for (int t = 0; t < 8; t++)
#pragma unroll
                    for (int q = 0; q < 4; q++) acc[i][t][q] = 0.0f;
        }
    }
}

// ---------------------------------------------------------------------------
// Launch. Inputs: x, base_weight, base_bias, vera_random_A, vera_random_B,
//                 vera_d, vera_b
// ---------------------------------------------------------------------------
extern "C" void kernel_launch(void* const* d_in, const int* in_sizes, int n_in,
                              void* d_out, int out_size)
{
    const float* x    = (const float*)d_in[0];
    const float* W    = (const float*)d_in[1];
    const float* bias = (const float*)d_in[2];
    const float* vA   = (const float*)d_in[3];
    const float* vB   = (const float*)d_in[4];
    const float* vd   = (const float*)d_in[5];
    const float* vb   = (const float*)d_in[6];
    float* y = (float*)d_out;

    cudaFuncSetAttribute(vera_all,
                         cudaFuncAttributeMaxDynamicSharedMemorySize, SMEM_MAIN);

    vera_all<<<NSM, BLK, SMEM_MAIN>>>(x, W, vA, vB, vd, vb, bias, y);
}

// round 17
// speedup vs baseline: 1.0932x; 1.0932x over previous
#include <cuda_runtime.h>
#include <cuda_fp16.h>
#include <cstdint>

#define T_DIM   8192
#define IN_DIM  4096
#define OUT_DIM 4096
#define R_DIM   256
#define SCALE_F 4.0f
#define NSM     148
#define NTILES  1024   /* main: 16 (o/256) x 64 (t/128) */
#define WGROUP  80     /* phase-B CTAs doing weff; rest do xprep */

// Tiled + SW128-pre-swizzled fp16 operand buffers (16KB tiles: 128 rows x 64 cols)
__device__ __align__(128) __half g_xhi[(size_t)T_DIM  * IN_DIM];
__device__ __align__(128) __half g_whi[(size_t)OUT_DIM * IN_DIM];
__device__ __align__(128) __half g_bh [(size_t)OUT_DIM * R_DIM];
__device__ __align__(128) __half g_ahT[(size_t)IN_DIM  * R_DIM];

// monotonic grid-barrier counter (replay-safe: target = ceil(ticket/NSM)*NSM)
__device__ int g_ctr;

// ---------------------------------------------------------------------------
// helpers
// ---------------------------------------------------------------------------
static __device__ __forceinline__ uint32_t sw128(uint32_t b) {
    return b ^ ((b >> 3) & 0x70);
}
static __device__ __forceinline__ uint32_t smem_u32(const void* p) {
    uint32_t a;
    asm("{ .reg .u64 t; cvta.to.shared.u64 t, %1; cvt.u32.u64 %0, t; }"
        : "=r"(a) : "l"(p));
    return a;
}
static __device__ __forceinline__ uint32_t h2u(__half a, __half b) {
    __half2 h = __halves2half2(a, b);
    return *(uint32_t*)&h;
}

#define MBARRIER_INIT(m, c) \
    asm volatile("mbarrier.init.shared.b64 [%0], %1;" :: "r"(m), "r"((uint32_t)(c)) : "memory")
#define MBARRIER_EXPECT_TX(m, b) \
    asm volatile("mbarrier.arrive.expect_tx.shared.b64 _, [%0], %1;" :: "r"(m), "r"((uint32_t)(b)) : "memory")
#define MBARRIER_ARRIVE(m) \
    asm volatile("mbarrier.arrive.shared.b64 _, [%0];" :: "r"(m) : "memory")

#define WAIT_PARITY(m, p) do {                                                    \
    uint32_t _m = (m), _p = (uint32_t)(p), _d;                                    \
    asm volatile("{\n\t.reg .pred P;\n\t"                                         \
        "mbarrier.try_wait.parity.acquire.cta.shared::cta.b64 P, [%1], %2;\n\t"   \
        "selp.b32 %0, 1, 0, P;\n\t}" : "=r"(_d) : "r"(_m), "r"(_p) : "memory");   \
    while (!_d) {                                                                 \
        asm volatile("{\n\t.reg .pred P;\n\t"                                     \
            "mbarrier.try_wait.parity.acquire.cta.shared::cta.b64 P, [%1], %2, 0x989680;\n\t" \
            "selp.b32 %0, 1, 0, P;\n\t}" : "=r"(_d) : "r"(_m), "r"(_p) : "memory"); \
    } } while (0)

static __device__ __forceinline__ void bulk_g2s(uint32_t dst, const void* src,
                                                uint32_t bytes, uint32_t mbar) {
    unsigned long long g = (unsigned long long)__cvta_generic_to_global(src);
    asm volatile("cp.async.bulk.shared::cta.global.mbarrier::complete_tx::bytes [%0], [%1], %2, [%3];"
                 :: "r"(dst), "l"(g), "r"(bytes), "r"(mbar) : "memory");
}

#define LDSM_X4(r, addr) \
    asm volatile("ldmatrix.sync.aligned.m8n8.x4.shared.b16 {%0,%1,%2,%3}, [%4];" \
                 : "=r"((r)[0]), "=r"((r)[1]), "=r"((r)[2]), "=r"((r)[3]) : "r"(addr))

#define MMA16816(c, a, b0, b1) \
    asm volatile("mma.sync.aligned.m16n8k16.row.col.f32.f16.f16.f32 " \
                 "{%0,%1,%2,%3}, {%4,%5,%6,%7}, {%8,%9}, {%0,%1,%2,%3};" \
                 : "+f"((c)[0]), "+f"((c)[1]), "+f"((c)[2]), "+f"((c)[3]) \
                 : "r"((a)[0]), "r"((a)[1]), "r"((a)[2]), "r"((a)[3]), \
                   "r"(b0), "r"(b1))

// device-wide barrier (all NSM CTAs resident at 1/SM)
static __device__ __forceinline__ void grid_bar() {
    __threadfence();
    __syncthreads();
    __shared__ int s_tgt;
    if (threadIdx.x == 0) {
        int t = atomicAdd(&g_ctr, 1) + 1;
        s_tgt = ((t + NSM - 1) / NSM) * NSM;
    }
    __syncthreads();
    if (threadIdx.x == 0) {
        const int tgt = s_tgt;
        int v;
        do {
            asm volatile("ld.global.acquire.gpu.b32 %0, [%1];" : "=r"(v) : "l"(&g_ctr));
        } while (v < tgt);
    }
    __syncthreads();
}

#define STAGES    4
#define STAGE_B   49152
#define WSTG_B    32768
#define SMEM_MAIN (1024 + STAGES * STAGE_B)

__global__ __launch_bounds__(256, 1) void vera_all(
    const float* __restrict__ x,  const float* __restrict__ W,
    const float* __restrict__ vA, const float* __restrict__ vB,
    const float* __restrict__ vd, const float* __restrict__ vb,
    const float* __restrict__ bias, float* __restrict__ y)
{
    extern __shared__ char smem[];
    const uint32_t sb = smem_u32(smem);
    const int tid  = threadIdx.x;
    const int lane = tid & 31;
    const int wid  = tid >> 5;
    const int bid  = blockIdx.x;

    const uint32_t FULL   = sb;
    const uint32_t EMPTY  = sb + 32;
    const uint32_t FULLB  = sb + 64;
    const uint32_t EMPTYB = sb + 112;
    const uint32_t STG0   = sb + 1024;

    if (tid == 0) {
        for (int s = 0; s < STAGES; s++) {
            MBARRIER_INIT(FULL  + 8 * s, 1);
            MBARRIER_INIT(EMPTY + 8 * s, 8);
        }
        for (int s = 0; s < 6; s++) {
            MBARRIER_INIT(FULLB  + 8 * s, 1);
            MBARRIER_INIT(EMPTYB + 8 * s, 8);
        }
    }
    __syncthreads();

    // ======================= PHASE A: Bh + AhT conversion ===================
    for (uint32_t c = bid * 256 + tid; c < 131072; c += NSM * 256) {
        const uint32_t o    = c >> 5;
        const uint32_t r8   = c & 31;
        const uint32_t rblk = r8 >> 3;
        const uint32_t cu   = (r8 & 7) * 8;
        const float s = __ldg(&vb[o]) * (SCALE_F / 64.0f);
        const float* src = vB + (size_t)o * R_DIM + rblk * 64 + cu;
        float4 a = *(const float4*)src;
        float4 b = *(const float4*)(src + 4);
        __half h[8] = {__float2half_rn(a.x * s), __float2half_rn(a.y * s),
                       __float2half_rn(a.z * s), __float2half_rn(a.w * s),
                       __float2half_rn(b.x * s), __float2half_rn(b.y * s),
                       __float2half_rn(b.z * s), __float2half_rn(b.w * s)};
        uint4 v = make_uint4(h2u(h[0], h[1]), h2u(h[2], h[3]),
                             h2u(h[4], h[5]), h2u(h[6], h[7]));
        const size_t tile = ((size_t)(o >> 7) * 4 + rblk) * 16384;
        *(uint4*)((char*)g_bh + tile + sw128((o & 127) * 128 + cu * 2)) = v;
    }
    for (uint32_t c = bid * 256 + tid; c < 131072; c += NSM * 256) {
        const uint32_t r8 = c >> 12;
        const uint32_t i  = c & 4095;
        uint32_t pk[4];
#pragma unroll
        for (int j = 0; j < 4; j++) {
            const uint32_t r0 = r8 * 8 + 2 * j;
            const float s0 = __ldg(&vd[r0])     * 64.0f;
            const float s1 = __ldg(&vd[r0 + 1]) * 64.0f;
            const float v0 = __ldg(&vA[(size_t)r0 * IN_DIM + i])       * s0;
            const float v1 = __ldg(&vA[(size_t)(r0 + 1) * IN_DIM + i]) * s1;
            pk[j] = h2u(__float2half_rn(v0), __float2half_rn(v1));
        }
        const size_t tile = ((size_t)(i >> 7) * 4 + (r8 >> 3)) * 16384;
        const uint32_t off = sw128((i & 127) * 128 + (r8 & 7) * 16);
        *(uint4*)((char*)g_ahT + tile + off) = make_uint4(pk[0], pk[1], pk[2], pk[3]);
    }

    grid_bar();

    // ============ PHASE B: weff HMMA (bid<WGROUP)  ||  xprep (rest) =========
    if (bid < WGROUP) {
        const int ntB   = (1023 - bid) / WGROUP + 1;  // 12 or 13
        const int NITB  = ntB * 4;

        if (lane == 0 && wid < 6) {
            const int q = wid;
            const int tile = bid + (q >> 2) * WGROUP;
            const int k    = q & 3;
            const uint32_t base = STG0 + wid * WSTG_B;
            MBARRIER_EXPECT_TX(FULLB + 8 * wid, WSTG_B);
            bulk_g2s(base,         (char*)g_bh  + (size_t)((tile >> 5) * 4 + k) * 16384, 16384, FULLB + 8 * wid);
            bulk_g2s(base + 16384, (char*)g_ahT + (size_t)((tile & 31) * 4 + k) * 16384, 16384, FULLB + 8 * wid);
        }

        const int warp_m = wid >> 2;
        const int warp_n = wid & 3;
        const int a_row      = warp_m * 64 + (lane & 15);
        const uint32_t a_rb  = (uint32_t)a_row * 128;
        const uint32_t amsk  = (uint32_t)(lane & 7) << 4;
        const uint32_t acol0 = (uint32_t)(lane >> 4) * 16;
        const int b_rowl     = warp_n * 32 + (lane & 7) + ((lane >> 4) & 1) * 8;
        const uint32_t b_rb  = (uint32_t)b_rowl * 128;
        const uint32_t bmsk  = (uint32_t)(lane & 7) << 4;
        const uint32_t bcol0 = (uint32_t)((lane >> 3) & 1) * 16;

        float acc[4][4][4];
#pragma unroll
        for (int i = 0; i < 4; i++)
#pragma unroll
            for (int t = 0; t < 4; t++)
#pragma unroll
                for (int q = 0; q < 4; q++) acc[i][t][q] = 0.0f;

#pragma unroll 1
        for (int p = 0; p < NITB; ++p) {
            const int s  = p % 6;
            const int ph = (p / 6) & 1;
            WAIT_PARITY(FULLB + 8 * s, ph);
            const uint32_t XA = STG0 + s * WSTG_B;
            const uint32_t WB = XA + 16384;
#pragma unroll
            for (int ks = 0; ks < 4; ks++) {
                const uint32_t acsw = (acol0 + ks * 32) ^ amsk;
                const uint32_t bcsw = (bcol0 + ks * 32) ^ bmsk;
                uint32_t A[4][4], B[2][4];
#pragma unroll
                for (int i = 0; i < 4; i++)
                    LDSM_X4(A[i], XA + a_rb + i * 2048 + acsw);
#pragma unroll
                for (int j = 0; j < 2; j++)
                    LDSM_X4(B[j], WB + b_rb + j * 2048 + bcsw);
                // early release: after this warp's final LDSM of the stage
                // (mbarrier.arrive has CTA-scope release; smem reads are done)
                if (ks == 3 && lane == 0) MBARRIER_ARRIVE(EMPTYB + 8 * s);
#pragma unroll
                for (int i = 0; i < 4; i++)
#pragma unroll
                    for (int j = 0; j < 2; j++) {
                        MMA16816(acc[i][2 * j],     A[i], B[j][0], B[j][1]);
                        MMA16816(acc[i][2 * j + 1], A[i], B[j][2], B[j][3]);
                    }
            }

            if (wid == s && lane == 0 && p + 6 < NITB) {
                WAIT_PARITY(EMPTYB + 8 * s, ph);
                const int q    = p + 6;
                const int tile = bid + (q >> 2) * WGROUP;
                const int k    = q & 3;
                const uint32_t base = STG0 + s * WSTG_B;
                MBARRIER_EXPECT_TX(FULLB + 8 * s, WSTG_B);
                bulk_g2s(base,         (char*)g_bh  + (size_t)((tile >> 5) * 4 + k) * 16384, 16384, FULLB + 8 * s);
                bulk_g2s(base + 16384, (char*)g_ahT + (size_t)((tile & 31) * 4 + k) * 16384, 16384, FULLB + 8 * s);
            }

            if ((p & 3) == 3) {   // tile epilogue: Weff = W + delta -> g_whi
                const int tile = bid + (p >> 2) * WGROUP;
                const int bO = tile >> 5;
                const int bI = tile & 31;
                const int trow0 = warp_m * 64 + (lane >> 2);
                const int col0  = warp_n * 32 + (lane & 3) * 2;
#pragma unroll
                for (int t = 0; t < 4; t++) {
                    const int col = col0 + t * 8;
                    const int ig  = bI * 128 + col;
                    const size_t gtile = ((size_t)bO * 64 + (ig >> 6)) * 16384;
                    const uint32_t cu2 = (uint32_t)(ig & 63) * 2;
#pragma unroll
                    for (int i = 0; i < 4; i++) {
                        const int r0 = trow0 + i * 16;
                        const float2 w0 = *(const float2*)&W[(size_t)(bO * 128 + r0) * IN_DIM + ig];
                        const float2 w1 = *(const float2*)&W[(size_t)(bO * 128 + r0 + 8) * IN_DIM + ig];
                        const uint32_t v0 = h2u(__float2half_rn(w0.x + acc[i][t][0]),
                                                __float2half_rn(w0.y + acc[i][t][1]));
                        const uint32_t v1 = h2u(__float2half_rn(w1.x + acc[i][t][2]),
                                                __float2half_rn(w1.y + acc[i][t][3]));
                        *(uint32_t*)((char*)g_whi + gtile + sw128((uint32_t)r0 * 128 + cu2))       = v0;
                        *(uint32_t*)((char*)g_whi + gtile + sw128((uint32_t)(r0 + 8) * 128 + cu2)) = v1;
                    }
                }
#pragma unroll
                for (int i = 0; i < 4; i++)
#pragma unroll
                    for (int t = 0; t < 4; t++)
#pragma unroll
                        for (int q = 0; q < 4; q++) acc[i][t][q] = 0.0f;
            }
        }
    } else {
        // xprep on 68 CTAs
        for (uint32_t c = (uint32_t)(bid - WGROUP) * 256 + tid; c < 4194304u;
             c += (uint32_t)(NSM - WGROUP) * 256) {
            const uint32_t k8   = c & 511;
            const uint32_t t    = c >> 9;
            const uint32_t kblk = k8 >> 3;
            const uint32_t cu   = (k8 & 7) * 8;
            const float* src = x + (size_t)t * IN_DIM + kblk * 64 + cu;
            float4 a = *(const float4*)src;
            float4 b = *(const float4*)(src + 4);
            __half2 p0 = __floats2half2_rn(a.x, a.y);
            __half2 p1 = __floats2half2_rn(a.z, a.w);
            __half2 p2 = __floats2half2_rn(b.x, b.y);
            __half2 p3 = __floats2half2_rn(b.z, b.w);
            uint4 v = make_uint4(*(uint32_t*)&p0, *(uint32_t*)&p1,
                                 *(uint32_t*)&p2, *(uint32_t*)&p3);
            const uint32_t off = sw128((t & 127) * 128 + cu * 2);
            *(uint4*)((char*)g_xhi + ((size_t)(t >> 7) * 64 + kblk) * 16384 + off) = v;
        }
    }

    grid_bar();

    // ======================= PHASE C: main GEMM =============================
    const int ntile = (NTILES - 1 - bid) / NSM + 1;   // 6 or 7
    const int NITER = ntile * 64;

    if (lane == 0 && wid < STAGES) {
        const int s = wid;
        const char* xs = (const char*)g_xhi + (size_t)((bid >> 4) * 64 + s) * 16384;
        const char* ws = (const char*)g_whi + (size_t)((bid & 15) * 2 * 64 + s) * 16384;
        const uint32_t base = STG0 + s * STAGE_B;
        MBARRIER_EXPECT_TX(FULL + 8 * s, STAGE_B);
        bulk_g2s(base,         xs, 16384, FULL + 8 * s);
        bulk_g2s(base + 16384, ws, 16384, FULL + 8 * s);
        bulk_g2s(base + 32768, ws + (size_t)64 * 16384, 16384, FULL + 8 * s);
    }

    const int warp_m = wid >> 2;
    const int warp_n = wid & 3;
    const int a_row      = warp_m * 64 + (lane & 15);
    const uint32_t a_rb  = (uint32_t)a_row * 128;
    const uint32_t amsk  = (uint32_t)(lane & 7) << 4;
    const uint32_t acol0 = (uint32_t)(lane >> 4) * 16;
    const int b_rowl     = (warp_n & 1) * 64 + (lane & 7) + ((lane >> 4) & 1) * 8;
    const uint32_t b_rb  = (uint32_t)((warp_n >> 1) * 16384 + b_rowl * 128);
    const uint32_t bmsk  = (uint32_t)(lane & 7) << 4;
    const uint32_t bcol0 = (uint32_t)((lane >> 3) & 1) * 16;

    float acc[4][8][4];
#pragma unroll
    for (int i = 0; i < 4; i++)
#pragma unroll
        for (int t = 0; t < 8; t++)
#pragma unroll
            for (int q = 0; q < 4; q++) acc[i][t][q] = 0.0f;

#pragma unroll 1
    for (int p = 0; p < NITER; ++p) {
        const int s  = p & 3;
        const int ph = (p >> 2) & 1;
        WAIT_PARITY(FULL + 8 * s, ph);
        const uint32_t XA = STG0 + s * STAGE_B;
        const uint32_t WB = XA + 16384;

#pragma unroll
        for (int ks = 0; ks < 4; ks++) {
            const uint32_t acsw = (acol0 + ks * 32) ^ amsk;
            const uint32_t bcsw = (bcol0 + ks * 32) ^ bmsk;
            uint32_t A[4][4], B[4][4];
#pragma unroll
            for (int i = 0; i < 4; i++)
                LDSM_X4(A[i], XA + a_rb + i * 2048 + acsw);
#pragma unroll
            for (int j = 0; j < 4; j++)
                LDSM_X4(B[j], WB + b_rb + j * 2048 + bcsw);
            // early release: stage smem is dead once this warp's last LDSM
            // has executed (arrive carries CTA-scope release ordering)
            if (ks == 3 && lane == 0) MBARRIER_ARRIVE(EMPTY + 8 * s);
#pragma unroll
            for (int i = 0; i < 4; i++)
#pragma unroll
                for (int j = 0; j < 4; j++) {
                    MMA16816(acc[i][2 * j],     A[i], B[j][0], B[j][1]);
                    MMA16816(acc[i][2 * j + 1], A[i], B[j][2], B[j][3]);
                }
        }

        // stage-distributed refill: warp s owns stage s
        if (wid == s && lane == 0 && p + STAGES < NITER) {
            WAIT_PARITY(EMPTY + 8 * s, ph);
            const int q    = p + STAGES;
            const int tile = bid + (q >> 6) * NSM;
            const int k    = q & 63;
            const char* xs = (const char*)g_xhi + (size_t)((tile >> 4) * 64 + k) * 16384;
            const char* ws = (const char*)g_whi + (size_t)((tile & 15) * 2 * 64 + k) * 16384;
            const uint32_t base = STG0 + s * STAGE_B;
            MBARRIER_EXPECT_TX(FULL + 8 * s, STAGE_B);
            bulk_g2s(base,         xs, 16384, FULL + 8 * s);
            bulk_g2s(base + 16384, ws, 16384, FULL + 8 * s);
            bulk_g2s(base + 32768, ws + (size_t)64 * 16384, 16384, FULL + 8 * s);
        }

        // tile epilogue
        if ((p & 63) == 63) {
            const int tile = bid + (p >> 6) * NSM;
            const int bM = tile >> 4;
            const int bN = tile & 15;
            const int trow0 = bM * 128 + warp_m * 64 + (lane >> 2);
            const int col0g = bN * 256 + warp_n * 64 + (lane & 3) * 2;
#pragma unroll
            for (int t = 0; t < 8; t++) {
                const int col = col0g + t * 8;
                const float2 bv = *(const float2*)&bias[col];
#pragma unroll
                for (int i = 0; i < 4; i++) {
                    const int r0 = trow0 + i * 16;
                    float2 o0 = make_float2(acc[i][t][0] + bv.x, acc[i][t][1] + bv.y);
                    float2 o1 = make_float2(acc[i][t][2] + bv.x, acc[i][t][3] + bv.y);
                    *(float2*)&y[(size_t)r0 * OUT_DIM + col]       = o0;
                    *(float2*)&y[(size_t)(r0 + 8) * OUT_DIM + col] = o1;
                }
            }
#pragma unroll
            for (int i = 0; i < 4; i++)
#pragma unroll
                for (int t = 0; t < 8; t++)
#pragma unroll
                    for (int q = 0; q < 4; q++) acc[i][t][q] = 0.0f;
        }
    }
}

// ---------------------------------------------------------------------------
// Launch. Inputs: x, base_weight, base_bias, vera_random_A, vera_random_B,
//                 vera_d, vera_b
// ---------------------------------------------------------------------------
extern "C" void kernel_launch(void* const* d_in, const int* in_sizes, int n_in,
                              void* d_out, int out_size)
{
    const float* x    = (const float*)d_in[0];
    const float* W    = (const float*)d_in[1];
    const float* bias = (const float*)d_in[2];
    const float* vA   = (const float*)d_in[3];
    const float* vB   = (const float*)d_in[4];
    const float* vd   = (const float*)d_in[5];
    const float* vb   = (const float*)d_in[6];
    float* y = (float*)d_out;

    cudaFuncSetAttribute(vera_all,
                         cudaFuncAttributeMaxDynamicSharedMemorySize, SMEM_MAIN);

    vera_all<<<NSM, 256, SMEM_MAIN>>>(x, W, vA, vB, vd, vb, bias, y);
}